// round 10
// baseline (speedup 1.0000x reference)
#include <cuda_runtime.h>
#include <float.h>

#define BB 4
#define DD 64
#define NN 4096
#define KNN 16
#define SPLIT 4
#define QT 128               /* queries per block */
#define CT 64                /* candidates per c-tile */
#define NCAND (NN / SPLIT)   /* 1024 */
#define NTILE (NCAND / CT)   /* 16 */
#define CAP 8                /* deferred stack depth */
#define EQT 8                /* edge: queries per block */

#define EF_ELEMS ((size_t)BB * 2 * DD * NN * KNN) /* 33,554,432 */

// Dynamic smem layout (floats unless noted):
//  sqA  [64][128]  query panel, d-major          ofs 0      (8192 f)
//  scB  [64][64]   candidate panel, d-major      ofs 8192   (4096 f)
//  sd2  [64][128]  dist tile, c-major            ofs 12288  (8192 f)
//  ssqq [128]                                    ofs 20480
//  ssqc [64]                                     ofs 20608
//  sstk u64[128][CAP]                            byte 82688 (8192 B)
//  sbst u64[128][16]                             byte 90880 (16384 B)
#define SMEM_BYTES 107264

// Scratch (allocation-free rule: __device__ globals)
__device__ float  g_sqn[BB * NN];
__device__ float  g_pdist[BB * SPLIT * NN * KNN];
__device__ int    g_pidx[BB * SPLIT * NN * KNN];
__device__ int    g_fidx[BB * NN * KNN];
__device__ float4 g_pcT4[BB * NN * (DD / 4)];   // pcT[b][n][d]

// ---------------------------------------------------------------------------
// Kernel 0: transpose pc[b][d][n] -> pcT[b][n][d]  (for edge gather)
// ---------------------------------------------------------------------------
__global__ void transpose_kernel(const float* __restrict__ pc) {
    __shared__ float tile[32][33];
    int b  = blockIdx.z;
    int d0 = blockIdx.y * 32;
    int n0 = blockIdx.x * 32;
    int tx = threadIdx.x, ty = threadIdx.y; // 32 x 8
    float* pT = (float*)g_pcT4;
#pragma unroll
    for (int r = 0; r < 4; ++r) {
        int y = ty + r * 8;
        tile[y][tx] = pc[((size_t)b * DD + d0 + y) * NN + n0 + tx];
    }
    __syncthreads();
#pragma unroll
    for (int r = 0; r < 4; ++r) {
        int y = ty + r * 8;
        pT[((size_t)b * NN + n0 + y) * DD + d0 + tx] = tile[tx][y];
    }
}

// ---------------------------------------------------------------------------
// Kernel 1: squared norms — EXACT sequential fp32 FMA chain over d ascending.
// ---------------------------------------------------------------------------
__global__ void sqnorm_kernel(const float* __restrict__ pc) {
    int t = blockIdx.x * blockDim.x + threadIdx.x;
    if (t >= BB * NN) return;
    int b = t / NN, n = t % NN;
    const float* p = pc + (size_t)b * DD * NN + n;
    float s = 0.f;
#pragma unroll
    for (int d = 0; d < DD; ++d) {
        float v = p[(size_t)d * NN];
        s = __fmaf_rn(v, v, s);
    }
    g_sqn[t] = s;
}

// ---------------------------------------------------------------------------
// Kernel 1b: scratch zero (keeps knn_partial at ncu's capture slot, launch 3)
// ---------------------------------------------------------------------------
__global__ void scratch_zero_kernel() {
    int t = blockIdx.x * blockDim.x + threadIdx.x;
    int total = BB * SPLIT * NN * KNN;
    if (t < total) { g_pdist[t] = 0.f; g_pidx[t] = 0; }
}

// ---------------------------------------------------------------------------
// Kernel 2: EXACT partial kNN, GEMM-tiled.
// Phase A: 8x8 register micro-tile per thread; acc[i][j] accumulates the dot
//          as ONE sequential fp32 FMA chain over d ascending (bit-exact ==
//          reference GEMM). Epilogue computes the exact key
//          dist = fp32_sqrt(max((sqq+sqc) - 2*acc, 0)) into smem tile.
// Phase B: thread-per-query scan (c ascending -> index-stable), deferred
//          push stack, u64 (dist_bits, idx) sorted top-16 in smem.
// ---------------------------------------------------------------------------
__global__ void __launch_bounds__(QT) knn_partial(const float* __restrict__ pc) {
    extern __shared__ float smem[];
    float* sqA  = smem;                 // [64][128]
    float* scB  = smem + 8192;          // [64][64]
    float* sd2  = smem + 12288;         // [64][128]
    float* ssqq = smem + 20480;         // [128]
    float* ssqc = smem + 20608;         // [64]
    unsigned long long* sstk = (unsigned long long*)(smem + 20672); // [128][CAP]
    unsigned long long* sbst = sstk + QT * CAP;                     // [128][16]

    const int tid = threadIdx.x;
    const int qt  = blockIdx.x;
    const int b   = blockIdx.y;
    const int sp  = blockIdx.z;
    const int q0  = qt * QT;
    const int qglob = q0 + tid;           // phase-B query of this thread

    const float* pcb = pc + (size_t)b * DD * NN;

    // Stage query panel (once) + norms
    for (int i = tid; i < DD * QT; i += QT) {
        int d = i >> 7, q = i & 127;
        sqA[i] = pcb[(size_t)d * NN + q0 + q];
    }
    ssqq[tid] = g_sqn[b * NN + qglob];

    // Init best list + stack
    unsigned long long* mybst = sbst + tid * 16;
    unsigned long long* mystk = sstk + tid * CAP;
#pragma unroll
    for (int k = 0; k < KNN; ++k) mybst[k] = 0xFFFFFFFFFFFFFFFFull;
    unsigned long long thresh = 0xFFFFFFFFFFFFFFFFull;
    int cnt = 0;

    const int qg = tid & 15;   // micro-tile query group (8 queries)
    const int cg = tid >> 4;   // micro-tile cand group  (8 cands)
    const float* qbase = sqA + qg * 8;
    const float* cbase = scB + cg * 8;

    for (int ct = 0; ct < NTILE; ++ct) {
        const int c0 = sp * NCAND + ct * CT;
        __syncthreads();   // sd2 reads of prev tile done before re-staging
        // Stage candidate panel + norms
        for (int i = tid; i < DD * CT; i += QT) {
            int d = i >> 6, c = i & 63;
            scB[i] = pcb[(size_t)d * NN + c0 + c];
        }
        if (tid < CT) ssqc[tid] = g_sqn[b * NN + c0 + tid];
        __syncthreads();

        // ---- Phase A: 8x8 micro-tile GEMM (exact chains) ----
        float acc[8][8];
#pragma unroll
        for (int i = 0; i < 8; ++i)
#pragma unroll
            for (int j = 0; j < 8; ++j) acc[i][j] = 0.f;

#pragma unroll 8
        for (int d = 0; d < DD; ++d) {
            float4 qa = *(const float4*)(qbase + d * QT);
            float4 qb = *(const float4*)(qbase + d * QT + 4);
            float4 ca = *(const float4*)(cbase + d * CT);
            float4 cb = *(const float4*)(cbase + d * CT + 4);
            float qf[8] = {qa.x, qa.y, qa.z, qa.w, qb.x, qb.y, qb.z, qb.w};
            float cf[8] = {ca.x, ca.y, ca.z, ca.w, cb.x, cb.y, cb.z, cb.w};
#pragma unroll
            for (int i = 0; i < 8; ++i)
#pragma unroll
                for (int j = 0; j < 8; ++j)
                    acc[i][j] = __fmaf_rn(qf[i], cf[j], acc[i][j]);
        }

        // Epilogue: exact key, store dist tile (c-major, q contiguous)
#pragma unroll
        for (int j = 0; j < 8; ++j) {
            float sc_ = ssqc[cg * 8 + j];
            float di[8];
#pragma unroll
            for (int i = 0; i < 8; ++i) {
                float d2 = __fsub_rn(__fadd_rn(ssqq[qg * 8 + i], sc_),
                                     __fmul_rn(2.0f, acc[i][j]));
                di[i] = __fsqrt_rn(fmaxf(d2, 0.0f));
            }
            float* dst = sd2 + (cg * 8 + j) * QT + qg * 8;
            *(float4*)(dst)     = make_float4(di[0], di[1], di[2], di[3]);
            *(float4*)(dst + 4) = make_float4(di[4], di[5], di[6], di[7]);
        }
        __syncthreads();

        // ---- Phase B: thread-per-query scan, deferred selection ----
#pragma unroll 1
        for (int c = 0; c < CT; ++c) {
            float dist = sd2[c * QT + tid];
            int ci = c0 + c;
            unsigned long long key =
                ((unsigned long long)__float_as_uint(dist) << 32) | (unsigned)ci;
            if (ci != qglob && key < thresh) {
                mystk[cnt++] = key;
                if (cnt == CAP) {   // overflow drain (warm-up only)
#pragma unroll 1
                    for (int e = 0; e < CAP; ++e) {
                        unsigned long long k2 = mystk[e];
                        if (k2 < mybst[KNN - 1]) {
                            bool placed = false;
#pragma unroll
                            for (int j = KNN - 1; j >= 1; --j) {
                                if (!placed) {
                                    unsigned long long pv = mybst[j - 1];
                                    if (k2 < pv) mybst[j] = pv;
                                    else { mybst[j] = k2; placed = true; }
                                }
                            }
                            if (!placed) mybst[0] = k2;
                        }
                    }
                    cnt = 0;
                    thresh = mybst[KNN - 1];
                }
            }
        }
        // batched drain once per tile
        if (cnt) {
#pragma unroll 1
            for (int e = 0; e < cnt; ++e) {
                unsigned long long k2 = mystk[e];
                if (k2 < mybst[KNN - 1]) {
                    bool placed = false;
#pragma unroll
                    for (int j = KNN - 1; j >= 1; --j) {
                        if (!placed) {
                            unsigned long long pv = mybst[j - 1];
                            if (k2 < pv) mybst[j] = pv;
                            else { mybst[j] = k2; placed = true; }
                        }
                    }
                    if (!placed) mybst[0] = k2;
                }
            }
            cnt = 0;
            thresh = mybst[KNN - 1];
        }
    }

    const size_t off = (((size_t)b * SPLIT + sp) * NN + qglob) * KNN;
#pragma unroll
    for (int k = 0; k < KNN; ++k) {
        unsigned long long k2 = mybst[k];
        g_pdist[off + k] = __uint_as_float((unsigned)(k2 >> 32));
        g_pidx[off + k]  = (int)(unsigned)(k2 & 0xFFFFFFFFull);
    }
}

// ---------------------------------------------------------------------------
// Kernel 3: merge SPLIT partial sorted lists -> final top-16, index-stable.
// ---------------------------------------------------------------------------
__global__ void knn_merge(float* __restrict__ out_idx) {
    int t = blockIdx.x * blockDim.x + threadIdx.x;
    if (t >= BB * NN) return;
    int b = t / NN, n = t % NN;

    float dloc[SPLIT * KNN];
    int   iloc[SPLIT * KNN];
#pragma unroll
    for (int s = 0; s < SPLIT; ++s) {
        size_t off = (((size_t)b * SPLIT + s) * NN + n) * KNN;
#pragma unroll
        for (int k = 0; k < KNN; ++k) {
            dloc[s * KNN + k] = g_pdist[off + k];
            iloc[s * KNN + k] = g_pidx[off + k];
        }
    }
    size_t obase = (size_t)t * KNN;
    for (int k = 0; k < KNN; ++k) {
        float bd = dloc[0];
        int   bp = 0;
        for (int j = 1; j < SPLIT * KNN; ++j) {
            if (dloc[j] < bd) { bd = dloc[j]; bp = j; }
        }
        int bi = iloc[bp];
        dloc[bp] = FLT_MAX;
        g_fidx[obase + k]  = bi;
        out_idx[obase + k] = (float)bi;
    }
}

// ---------------------------------------------------------------------------
// Kernel 4: edge features (gather from pcT, coalesced writes).
// ---------------------------------------------------------------------------
__global__ void __launch_bounds__(256) edge_kernel(float* __restrict__ out) {
    __shared__ float snb[EQT * KNN][65];
    __shared__ float scen[EQT][65];
    __shared__ int   sidx[EQT * KNN];

    const int b  = blockIdx.y;
    const int n0 = blockIdx.x * EQT;
    const int tid = threadIdx.x;

    if (tid < EQT * KNN)
        sidx[tid] = g_fidx[((size_t)b * NN + n0 + tid / KNN) * KNN + tid % KNN];
    if (tid < EQT * 16) {
        int qq = tid / 16, f4 = tid % 16;
        float4 v = g_pcT4[((size_t)b * NN + n0 + qq) * 16 + f4];
        float* dst = &scen[qq][f4 * 4];
        dst[0] = v.x; dst[1] = v.y; dst[2] = v.z; dst[3] = v.w;
    }
    __syncthreads();

#pragma unroll
    for (int it = 0; it < 8; ++it) {
        int flat = it * 256 + tid;
        int row = flat >> 4;
        int f4  = flat & 15;
        int c = sidx[row];
        float4 v = g_pcT4[((size_t)b * NN + c) * 16 + f4];
        float* dst = &snb[row][f4 * 4];
        dst[0] = v.x; dst[1] = v.y; dst[2] = v.z; dst[3] = v.w;
    }
    __syncthreads();

    float4* out4 = (float4*)out;
#pragma unroll
    for (int t = 0; t < 16; ++t) {
        int i  = t * 256 + tid;
        int k4 = i & 3;
        int nn = (i >> 2) & 7;
        int d2 = i >> 5;
        int d  = d2 & 63;
        float cen = scen[nn][d];
        float4 o;
        if (d2 < 64) {
            o = make_float4(cen, cen, cen, cen);
        } else {
            int row = nn * KNN + k4 * 4;
            o.x = snb[row + 0][d] - cen;
            o.y = snb[row + 1][d] - cen;
            o.z = snb[row + 2][d] - cen;
            o.w = snb[row + 3][d] - cen;
        }
        out4[(((size_t)b * 128 + d2) * NN + n0 + nn) * 4 + k4] = o;
    }
}

// ---------------------------------------------------------------------------
extern "C" void kernel_launch(void* const* d_in, const int* in_sizes, int n_in,
                              void* d_out, int out_size) {
    const float* pc = (const float*)d_in[0];
    float* out = (float*)d_out;

    cudaFuncSetAttribute(knn_partial,
                         cudaFuncAttributeMaxDynamicSharedMemorySize, SMEM_BYTES);

    {
        dim3 g(NN / 32, DD / 32, BB), t(32, 8);
        transpose_kernel<<<g, t>>>(pc);                       // launch 0
    }
    sqnorm_kernel<<<(BB * NN + 255) / 256, 256>>>(pc);        // launch 1
    scratch_zero_kernel<<<(BB * SPLIT * NN * KNN + 255) / 256, 256>>>(); // 2

    {
        dim3 grid(NN / QT, BB, SPLIT);
        knn_partial<<<grid, QT, SMEM_BYTES>>>(pc);            // launch 3 (profiled)
    }

    knn_merge<<<(BB * NN + 255) / 256, 256>>>(out + EF_ELEMS);

    {
        dim3 g(NN / EQT, BB);
        edge_kernel<<<g, 256>>>(out);
    }
}

// round 13
// speedup vs baseline: 1.0595x; 1.0595x over previous
#include <cuda_runtime.h>
#include <float.h>

#define BB 4
#define DD 64
#define NN 4096
#define KNN 16
#define SPLIT 4
#define NLIST (SPLIT * 2)    /* 8 partial lists per query */
#define QT 128               /* queries per block */
#define CT 64                /* candidates per c-tile */
#define NCAND (NN / SPLIT)   /* 1024 */
#define NTILE (NCAND / CT)   /* 16 */
#define NTHR 256
#define CAP 8                /* deferred stack depth */
#define EQT 8                /* edge: queries per block */
#define BN (BB * NN)

#define EF_ELEMS ((size_t)BB * 2 * DD * NN * KNN) /* 33,554,432 */

// smem: sqA[64][128] | scB[64][64] | sd2[64][128] | ssqq[128] | ssqc[64] | stack u64[256][8]
#define SMEM_FLOATS (8192 + 4096 + 8192 + 128 + 64)  /* 20672 */
#define SMEM_BYTES  (SMEM_FLOATS * 4 + NTHR * CAP * 8) /* 99072 */

// Scratch (allocation-free rule: __device__ globals)
__device__ float              g_sqn[BN];
__device__ unsigned long long g_pkey[NLIST * KNN * BN];  // [list][rank][b*NN+n]
__device__ int                g_fidx[BN * KNN];
__device__ float4             g_pcT4[BN * (DD / 4)];     // pcT[b][n][d]

// ---------------------------------------------------------------------------
// Kernel 0: transpose pc[b][d][n] -> pcT[b][n][d]  (for edge gather)
// ---------------------------------------------------------------------------
__global__ void transpose_kernel(const float* __restrict__ pc) {
    __shared__ float tile[32][33];
    int b  = blockIdx.z;
    int d0 = blockIdx.y * 32;
    int n0 = blockIdx.x * 32;
    int tx = threadIdx.x, ty = threadIdx.y; // 32 x 8
    float* pT = (float*)g_pcT4;
#pragma unroll
    for (int r = 0; r < 4; ++r) {
        int y = ty + r * 8;
        tile[y][tx] = pc[((size_t)b * DD + d0 + y) * NN + n0 + tx];
    }
    __syncthreads();
#pragma unroll
    for (int r = 0; r < 4; ++r) {
        int y = ty + r * 8;
        pT[((size_t)b * NN + n0 + y) * DD + d0 + tx] = tile[tx][y];
    }
}

// ---------------------------------------------------------------------------
// Kernel 1: squared norms — EXACT sequential fp32 FMA chain over d ascending.
// ---------------------------------------------------------------------------
__global__ void sqnorm_kernel(const float* __restrict__ pc) {
    int t = blockIdx.x * blockDim.x + threadIdx.x;
    if (t >= BN) return;
    int b = t / NN, n = t % NN;
    const float* p = pc + (size_t)b * DD * NN + n;
    float s = 0.f;
#pragma unroll
    for (int d = 0; d < DD; ++d) {
        float v = p[(size_t)d * NN];
        s = __fmaf_rn(v, v, s);
    }
    g_sqn[t] = s;
}

// ---------------------------------------------------------------------------
// Kernel 1b: scratch touch (keeps knn_partial at ncu capture slot, launch 3)
// ---------------------------------------------------------------------------
__global__ void scratch_zero_kernel() {
    int t = blockIdx.x * blockDim.x + threadIdx.x;
    if (t < BN * KNN) g_fidx[t] = 0;
}

// ---------------------------------------------------------------------------
// Register best-16 (u64 keys), insert-after-equal == jax stable top_k.
// ---------------------------------------------------------------------------
__device__ __forceinline__ void insert16r(unsigned long long* best, unsigned long long k2) {
    if (k2 < best[KNN - 1]) {
        bool placed = false;
#pragma unroll
        for (int j = KNN - 1; j >= 1; --j) {
            if (!placed) {
                unsigned long long pv = best[j - 1];
                if (k2 < pv) best[j] = pv;
                else { best[j] = k2; placed = true; }
            }
        }
        if (!placed) best[0] = k2;
    }
}

// ---------------------------------------------------------------------------
// Kernel 2: EXACT partial kNN, GEMM-tiled, 256 threads, 2 blocks/SM.
// Phase A: 8q x 4c register micro-tile; each acc is ONE sequential fp32 FMA
//          chain over d ascending (bit-exact == reference GEMM). Epilogue:
//          dist = fp32_sqrt(max((sqq+sqc) - 2*acc, 0)) -> smem tile.
// Phase B: 2 threads per query (one per 32-cand half), deferred stack,
//          register best-16 of u64 (dist_bits, idx) keys.
// ---------------------------------------------------------------------------
__global__ void __launch_bounds__(NTHR) knn_partial(const float* __restrict__ pc) {
    extern __shared__ float smem[];
    float* sqA  = smem;                  // [64][128]
    float* scB  = smem + 8192;           // [64][64]
    float* sd2  = smem + 12288;          // [64][128] c-major
    float* ssqq = smem + 20480;          // [128]
    float* ssqc = smem + 20608;          // [64]
    unsigned long long* sstk = (unsigned long long*)(smem + SMEM_FLOATS);

    const int tid = threadIdx.x;
    const int qtile = blockIdx.x;
    const int b   = blockIdx.y;
    const int sp  = blockIdx.z;
    const int q0  = qtile * QT;

    const float* pcb = pc + (size_t)b * DD * NN;

    // Stage query panel + norms (once)
    for (int i = tid; i < DD * QT; i += NTHR) {
        int d = i >> 7, q = i & 127;
        sqA[i] = pcb[(size_t)d * NN + q0 + q];
    }
    if (tid < QT) ssqq[tid] = g_sqn[b * NN + q0 + tid];

    const int qg = tid & 15;    // 16 query groups x 8
    const int cg = tid >> 4;    // 16 cand groups x 4
    const float* qbase = sqA + qg * 8;
    const float* cbase = scB + cg * 4;

    // Phase-B identity: 2 threads per query
    const int nq   = tid & 127;       // query within block
    const int half = tid >> 7;        // candidate half (0: c<32, 1: c>=32)
    const int qglob = q0 + nq;

    unsigned long long best[KNN];
#pragma unroll
    for (int k = 0; k < KNN; ++k) best[k] = 0xFFFFFFFFFFFFFFFFull;
    unsigned long long thresh = 0xFFFFFFFFFFFFFFFFull;
    unsigned long long* mystk = sstk + tid * CAP;
    int cnt = 0;

    for (int ct = 0; ct < NTILE; ++ct) {
        const int c0 = sp * NCAND + ct * CT;
        __syncthreads();   // prev-tile sd2 reads done before restage
        for (int i = tid; i < DD * CT; i += NTHR) {
            int d = i >> 6, c = i & 63;
            scB[i] = pcb[(size_t)d * NN + c0 + c];
        }
        if (tid < CT) ssqc[tid] = g_sqn[b * NN + c0 + tid];
        __syncthreads();

        // ---- Phase A: 8x4 micro-tile, exact sequential chains over d ----
        float acc[8][4];
#pragma unroll
        for (int i = 0; i < 8; ++i)
#pragma unroll
            for (int j = 0; j < 4; ++j) acc[i][j] = 0.f;

#pragma unroll 8
        for (int d = 0; d < DD; ++d) {
            float4 qa = *(const float4*)(qbase + d * QT);
            float4 qb = *(const float4*)(qbase + d * QT + 4);
            float4 ca = *(const float4*)(cbase + d * CT);
            float qf[8] = {qa.x, qa.y, qa.z, qa.w, qb.x, qb.y, qb.z, qb.w};
            float cf[4] = {ca.x, ca.y, ca.z, ca.w};
#pragma unroll
            for (int i = 0; i < 8; ++i)
#pragma unroll
                for (int j = 0; j < 4; ++j)
                    acc[i][j] = __fmaf_rn(qf[i], cf[j], acc[i][j]);
        }

        // Epilogue: exact keys into sd2 (c-major rows, q contiguous)
#pragma unroll
        for (int j = 0; j < 4; ++j) {
            float sc_ = ssqc[cg * 4 + j];
            float di[8];
#pragma unroll
            for (int i = 0; i < 8; ++i) {
                float d2 = __fsub_rn(__fadd_rn(ssqq[qg * 8 + i], sc_),
                                     __fmul_rn(2.0f, acc[i][j]));
                di[i] = __fsqrt_rn(fmaxf(d2, 0.0f));
            }
            float* dst = sd2 + (cg * 4 + j) * QT + qg * 8;
            *(float4*)(dst)     = make_float4(di[0], di[1], di[2], di[3]);
            *(float4*)(dst + 4) = make_float4(di[4], di[5], di[6], di[7]);
        }
        __syncthreads();

        // ---- Phase B: scan my 32-candidate half (c ascending) ----
#pragma unroll 1
        for (int cc = 0; cc < 32; ++cc) {
            int c = half * 32 + cc;
            float dist = sd2[c * QT + nq];
            int ci = c0 + c;
            unsigned long long key =
                ((unsigned long long)__float_as_uint(dist) << 32) | (unsigned)ci;
            if (ci != qglob && key < thresh) {
                mystk[cnt++] = key;
                if (cnt == CAP) {   // overflow drain (warm-up only)
#pragma unroll 1
                    for (int e = 0; e < CAP; ++e) insert16r(best, mystk[e]);
                    cnt = 0;
                    thresh = best[KNN - 1];
                }
            }
        }
        if (cnt) {
#pragma unroll 1
            for (int e = 0; e < cnt; ++e) insert16r(best, mystk[e]);
            cnt = 0;
            thresh = best[KNN - 1];
        }
    }

    // Write partial list: [list][rank][b*NN+q], coalesced over q
    const int s2 = sp * 2 + half;
    const int gq = b * NN + qglob;
#pragma unroll
    for (int k = 0; k < KNN; ++k)
        g_pkey[((size_t)s2 * KNN + k) * BN + gq] = best[k];
}

// ---------------------------------------------------------------------------
// Kernel 3: 8-way sorted-list merge -> final top-16. u64 keys embed index,
// so min-selection is exactly the reference's stable order.
// ---------------------------------------------------------------------------
__global__ void knn_merge(float* __restrict__ out_idx) {
    int t = blockIdx.x * blockDim.x + threadIdx.x;
    if (t >= BN) return;

    int pos[NLIST];
    unsigned long long cur[NLIST];
#pragma unroll
    for (int s = 0; s < NLIST; ++s) {
        pos[s] = 0;
        cur[s] = g_pkey[((size_t)s * KNN + 0) * BN + t];
    }
    size_t obase = (size_t)t * KNN;
#pragma unroll 1
    for (int k = 0; k < KNN; ++k) {
        int bs = 0;
        unsigned long long bk = cur[0];
#pragma unroll
        for (int s = 1; s < NLIST; ++s)
            if (cur[s] < bk) { bk = cur[s]; bs = s; }
        int bi = (int)(unsigned)(bk & 0xFFFFFFFFull);
        g_fidx[obase + k]  = bi;
        out_idx[obase + k] = (float)bi;
        int p = ++pos[bs];
        cur[bs] = (p < KNN) ? g_pkey[((size_t)bs * KNN + p) * BN + t]
                            : 0xFFFFFFFFFFFFFFFFull;
    }
}

// ---------------------------------------------------------------------------
// Kernel 4: edge features (gather from pcT, coalesced writes).
// ---------------------------------------------------------------------------
__global__ void __launch_bounds__(256) edge_kernel(float* __restrict__ out) {
    __shared__ float snb[EQT * KNN][65];
    __shared__ float scen[EQT][65];
    __shared__ int   sidx[EQT * KNN];

    const int b  = blockIdx.y;
    const int n0 = blockIdx.x * EQT;
    const int tid = threadIdx.x;

    if (tid < EQT * KNN)
        sidx[tid] = g_fidx[((size_t)b * NN + n0 + tid / KNN) * KNN + tid % KNN];
    if (tid < EQT * 16) {
        int qq = tid / 16, f4 = tid % 16;
        float4 v = g_pcT4[((size_t)b * NN + n0 + qq) * 16 + f4];
        float* dst = &scen[qq][f4 * 4];
        dst[0] = v.x; dst[1] = v.y; dst[2] = v.z; dst[3] = v.w;
    }
    __syncthreads();

#pragma unroll
    for (int it = 0; it < 8; ++it) {
        int flat = it * 256 + tid;
        int row = flat >> 4;
        int f4  = flat & 15;
        int c = sidx[row];
        float4 v = g_pcT4[((size_t)b * NN + c) * 16 + f4];
        float* dst = &snb[row][f4 * 4];
        dst[0] = v.x; dst[1] = v.y; dst[2] = v.z; dst[3] = v.w;
    }
    __syncthreads();

    float4* out4 = (float4*)out;
#pragma unroll
    for (int t = 0; t < 16; ++t) {
        int i  = t * 256 + tid;
        int k4 = i & 3;
        int nn = (i >> 2) & 7;
        int d2 = i >> 5;
        int d  = d2 & 63;
        float cen = scen[nn][d];
        float4 o;
        if (d2 < 64) {
            o = make_float4(cen, cen, cen, cen);
        } else {
            int row = nn * KNN + k4 * 4;
            o.x = snb[row + 0][d] - cen;
            o.y = snb[row + 1][d] - cen;
            o.z = snb[row + 2][d] - cen;
            o.w = snb[row + 3][d] - cen;
        }
        out4[(((size_t)b * 128 + d2) * NN + n0 + nn) * 4 + k4] = o;
    }
}

// ---------------------------------------------------------------------------
extern "C" void kernel_launch(void* const* d_in, const int* in_sizes, int n_in,
                              void* d_out, int out_size) {
    const float* pc = (const float*)d_in[0];
    float* out = (float*)d_out;

    cudaFuncSetAttribute(knn_partial,
                         cudaFuncAttributeMaxDynamicSharedMemorySize, SMEM_BYTES);

    {
        dim3 g(NN / 32, DD / 32, BB), t(32, 8);
        transpose_kernel<<<g, t>>>(pc);                       // launch 0
    }
    sqnorm_kernel<<<(BN + 255) / 256, 256>>>(pc);             // launch 1
    scratch_zero_kernel<<<(BN * KNN + 255) / 256, 256>>>();   // launch 2

    {
        dim3 grid(NN / QT, BB, SPLIT);
        knn_partial<<<grid, NTHR, SMEM_BYTES>>>(pc);          // launch 3 (profiled)
    }

    knn_merge<<<(BN + 255) / 256, 256>>>(out + EF_ELEMS);

    {
        dim3 g(NN / EQT, BB);
        edge_kernel<<<g, 256>>>(out);
    }
}